// round 8
// baseline (speedup 1.0000x reference)
#include <cuda_runtime.h>

// Problem constants (fixed by setup_inputs): B=4, C=128, W=H=64
#define NB  4
#define NCH 64      // c_half = c_out
#define ND  8       // d_qk
#define NN  4096    // W*H tokens
#define MT  64      // query tile (rows per block)
#define NT  64      // key tile
#define NSPLIT 2    // key-dimension split across blocks
#define HT  (NN / NT / NSPLIT)   // 32 key tiles per half
#define VPAD 68
#define WPAD 68

// Scratch (no cudaMalloc allowed) — 16B aligned for vector access.
__device__ __align__(16) float g_p2t[NB * NN * ND];          // [b][n][8]
__device__ __align__(16) float g_p3t[NB * NN * ND];          // [b][n][8]
__device__ __align__(16) float g_v3t[NB * NN * NCH];         // [b][n][64]
__device__ __align__(16) float g_s32[NSPLIT * NB * NN];      // partial denoms
__device__ __align__(16) float g_s33[NSPLIT * NB * NN];
__device__ __align__(16) float g_part[NSPLIT * NB * NCH * NN]; // partial outputs

// ---------------------------------------------------------------------------
// K1: 1x1-conv projections, written n-major. 128 threads, 128 blocks/batch.
// ---------------------------------------------------------------------------
__global__ void proj_kernel(const float* __restrict__ x,
                            const float* __restrict__ wq2, const float* __restrict__ bq2,
                            const float* __restrict__ wq3, const float* __restrict__ bq3,
                            const float* __restrict__ wv3, const float* __restrict__ bv3)
{
    __shared__ float s_wq2[ND * NCH];
    __shared__ float s_wq3[ND * NCH];
    __shared__ float s_wv3[NCH * NCH];
    __shared__ float s_b[2 * ND + NCH];

    const int tid = threadIdx.x;
    for (int i = tid; i < ND * NCH; i += 128) { s_wq2[i] = wq2[i]; s_wq3[i] = wq3[i]; }
    for (int i = tid; i < NCH * NCH; i += 128) s_wv3[i] = wv3[i];
    if (tid < ND)                s_b[tid] = bq2[tid];
    else if (tid < 2 * ND)       s_b[tid] = bq3[tid - ND];
    else if (tid < 2 * ND + NCH) s_b[tid] = bv3[tid - 2 * ND];
    __syncthreads();

    const int b = blockIdx.y;
    const int n = blockIdx.x * 128 + tid;
    const float* xb = x + (size_t)b * (2 * NCH) * NN;

    float p2[ND], p3[ND], v[NCH];
#pragma unroll
    for (int d = 0; d < ND; d++) { p2[d] = s_b[d]; p3[d] = s_b[ND + d]; }
#pragma unroll
    for (int c = 0; c < NCH; c++) v[c] = s_b[2 * ND + c];

    for (int c = 0; c < NCH; c++) {
        const float x3v = xb[c * NN + n];
        const float x2v = xb[(NCH + c) * NN + n];
#pragma unroll
        for (int d = 0; d < ND; d++) {
            p2[d] = fmaf(s_wq2[d * NCH + c], x2v, p2[d]);
            p3[d] = fmaf(s_wq3[d * NCH + c], x3v, p3[d]);
        }
#pragma unroll
        for (int o = 0; o < NCH; o++)
            v[o] = fmaf(s_wv3[o * NCH + c], x3v, v[o]);
    }

    float* o2 = g_p2t + ((size_t)b * NN + n) * ND;
    float* o3 = g_p3t + ((size_t)b * NN + n) * ND;
    float* ov = g_v3t + ((size_t)b * NN + n) * NCH;
#pragma unroll
    for (int d = 0; d < ND; d++) { o2[d] = p2[d]; o3[d] = p3[d]; }
#pragma unroll
    for (int c = 0; c < NCH; c++) ov[c] = v[c];
}

__device__ __forceinline__ float dot8(const float4 a, const float4 b,
                                      const float4 c, const float4 d)
{
    float s = a.x * c.x;
    s = fmaf(a.y, c.y, s);
    s = fmaf(a.z, c.z, s);
    s = fmaf(a.w, c.w, s);
    s = fmaf(b.x, d.x, s);
    s = fmaf(b.y, d.y, s);
    s = fmaf(b.z, d.z, s);
    s = fmaf(b.w, d.w, s);
    return s;
}

// ---------------------------------------------------------------------------
// K2: partial softmax denominators over this block's key half.
//   grid (NN/MT, NB, NSPLIT), 256 threads.
//   mq = tid&15 -> 4 query rows m=mq*4+k;  np = tid>>4 -> keys n=i*16+np.
// ---------------------------------------------------------------------------
__global__ __launch_bounds__(256) void sum_kernel()
{
    __shared__ __align__(16) float s_p2[2][NT * ND];
    __shared__ __align__(16) float s_p3[2][NT * ND];
    __shared__ __align__(16) float s_red[16 * 8 * 8];

    const int tid = threadIdx.x;
    const int b   = blockIdx.y;
    const int h   = blockIdx.z;
    const int m0  = blockIdx.x * MT;
    const int mq  = tid & 15;
    const int np  = tid >> 4;

    const float4* p2g = (const float4*)g_p2t + (size_t)b * NN * 2;
    const float4* p3g = (const float4*)g_p3t + (size_t)b * NN * 2;

    float4 qa[4], qb[4];
#pragma unroll
    for (int k = 0; k < 4; k++) {
        qa[k] = p3g[(m0 + mq * 4 + k) * 2 + 0];
        qb[k] = p3g[(m0 + mq * 4 + k) * 2 + 1];
    }

    float sum32[4] = {0.f, 0.f, 0.f, 0.f};
    float sum33[4] = {0.f, 0.f, 0.f, 0.f};
    const int t0 = h * HT;
    float4 pr = (tid < 128) ? p2g[t0 * 128 + tid] : p3g[t0 * 128 + tid - 128];
    if (tid < 128) ((float4*)s_p2[0])[tid]       = pr;
    else           ((float4*)s_p3[0])[tid - 128] = pr;
    __syncthreads();
    for (int t = 0; t < HT; t++) {
        const int cur = t & 1;
        if (t + 1 < HT) {
            const int base = (t0 + t + 1) * 128;
            pr = (tid < 128) ? p2g[base + tid] : p3g[base + tid - 128];
        }
#pragma unroll
        for (int i = 0; i < 4; i++) {
            const int n = i * 16 + np;
            const float4 k2a = ((const float4*)s_p2[cur])[n * 2];
            const float4 k2b = ((const float4*)s_p2[cur])[n * 2 + 1];
            const float4 k3a = ((const float4*)s_p3[cur])[n * 2];
            const float4 k3b = ((const float4*)s_p3[cur])[n * 2 + 1];
#pragma unroll
            for (int k = 0; k < 4; k++) {
                sum32[k] += __expf(dot8(qa[k], qb[k], k2a, k2b));
                sum33[k] += __expf(dot8(qa[k], qb[k], k3a, k3b));
            }
        }
        if (t + 1 < HT) {
            if (tid < 128) ((float4*)s_p2[cur ^ 1])[tid]       = pr;
            else           ((float4*)s_p3[cur ^ 1])[tid - 128] = pr;
        }
        __syncthreads();
    }
#pragma unroll
    for (int k = 0; k < 4; k++) {
        sum32[k] += __shfl_xor_sync(0xffffffffu, sum32[k], 16);
        sum33[k] += __shfl_xor_sync(0xffffffffu, sum33[k], 16);
    }
    const int warp = tid >> 5, lane = tid & 31;
    if (lane < 16) {
#pragma unroll
        for (int k = 0; k < 4; k++) {
            s_red[(lane * 8 + warp) * 8 + k]     = sum32[k];
            s_red[(lane * 8 + warp) * 8 + 4 + k] = sum33[k];
        }
    }
    __syncthreads();
    if (tid < 128) {
        const int m = tid >> 1, type = tid & 1;
        const int mq_ = m >> 2, k_ = m & 3;
        float s = 0.f;
#pragma unroll
        for (int w = 0; w < 8; w++)
            s += s_red[(mq_ * 8 + w) * 8 + type * 4 + k_];
        const int gi = h * NB * NN + b * NN + m0 + m;
        if (type == 0) g_s32[gi] = s;
        else           g_s33[gi] = s;
    }
}

// ---------------------------------------------------------------------------
// K3: combined-weight partial GEMM over this block's key half.
//   grid (NN/MT, NB, NSPLIT), 256 threads, 3 blocks/SM.
//   Weight gen: mq/np roles.  GEMM: half=tid>>7 splits tile; mg 8m, cg 4c.
// ---------------------------------------------------------------------------
__global__ __launch_bounds__(256, 3) void gemm_kernel(const float* __restrict__ g2p,
                                                      const float* __restrict__ g3p)
{
    __shared__ __align__(16) float s_p2[2][NT * ND];
    __shared__ __align__(16) float s_p3[2][NT * ND];
    __shared__ __align__(16) float s_v[NT][VPAD];
    __shared__ __align__(16) float s_w[NT][WPAD];
    __shared__ __align__(16) float s_q[MT * ND];
    __shared__ __align__(16) float s_sc32[MT];
    __shared__ __align__(16) float s_sc33[MT];

    const int tid = threadIdx.x;
    const int b   = blockIdx.y;
    const int h   = blockIdx.z;
    const int m0  = blockIdx.x * MT;
    const int mq  = tid & 15;
    const int np  = tid >> 4;

    const float4* p2g = (const float4*)g_p2t + (size_t)b * NN * 2;
    const float4* p3g = (const float4*)g_p3t + (size_t)b * NN * 2;
    const float4* vg  = (const float4*)g_v3t + (size_t)b * NN * (NCH / 4);

    // load q rows + combined softmax scales
    if (tid < 128)
        ((float4*)s_q)[tid] = p3g[(m0 + (tid >> 1)) * 2 + (tid & 1)];
    else if (tid < 192) {
        const int m  = tid - 128;
        const int gi = b * NN + m0 + m;
        const float z32 = g_s32[gi] + g_s32[NB * NN + gi];
        const float z33 = g_s33[gi] + g_s33[NB * NN + gi];
        s_sc32[m] = (*g2p) / z32;
        s_sc33[m] = (*g3p) / z33;
    }

    const int half = tid >> 7;
    const int t7   = tid & 127;
    const int mg   = t7 & 7;
    const int cg   = t7 >> 3;
    const int nlo  = half * 32;
    const int t0   = h * HT;

    float acc[8][4];
#pragma unroll
    for (int r = 0; r < 8; r++)
#pragma unroll
        for (int j = 0; j < 4; j++) acc[r][j] = 0.f;

    // preamble: p-tile0 -> buf0, prefetch p-tile1 + v-tile0
    float4 pr = (tid < 128) ? p2g[t0 * 128 + tid] : p3g[t0 * 128 + tid - 128];
    float4 vr[4];
#pragma unroll
    for (int k = 0; k < 4; k++) vr[k] = vg[t0 * 1024 + tid + k * 256];
    if (tid < 128) ((float4*)s_p2[0])[tid]       = pr;
    else           ((float4*)s_p3[0])[tid - 128] = pr;
    pr = (tid < 128) ? p2g[(t0 + 1) * 128 + tid] : p3g[(t0 + 1) * 128 + tid - 128];
    __syncthreads();   // p buf0, s_q, s_sc ready

    for (int t = 0; t < HT; t++) {
        const int cur = t & 1;
#pragma unroll
        for (int k = 0; k < 4; k++) {
            const int fi = tid + k * 256;
            *(float4*)(&s_v[fi >> 4][(fi & 15) * 4]) = vr[k];
        }
        if (t + 1 < HT) {
            if (tid < 128) ((float4*)s_p2[cur ^ 1])[tid]       = pr;
            else           ((float4*)s_p3[cur ^ 1])[tid - 128] = pr;
        }

        // weight gen for tile t, two query rows at a time
#pragma unroll
        for (int kh = 0; kh < 2; kh++) {
            const int mrow = mq * 4 + kh * 2;
            const float4 q0a = ((const float4*)(s_q + (size_t)mrow * ND))[0];
            const float4 q0b = ((const float4*)(s_q + (size_t)mrow * ND))[1];
            const float4 q1a = ((const float4*)(s_q + (size_t)(mrow + 1) * ND))[0];
            const float4 q1b = ((const float4*)(s_q + (size_t)(mrow + 1) * ND))[1];
            const float2 sA = *(const float2*)&s_sc32[mrow];
            const float2 sB = *(const float2*)&s_sc33[mrow];
#pragma unroll
            for (int i = 0; i < 4; i++) {
                const int n = i * 16 + np;
                const float4 k2a = ((const float4*)s_p2[cur])[n * 2];
                const float4 k2b = ((const float4*)s_p2[cur])[n * 2 + 1];
                const float4 k3a = ((const float4*)s_p3[cur])[n * 2];
                const float4 k3b = ((const float4*)s_p3[cur])[n * 2 + 1];
                float2 wv;
                wv.x = fmaf(sA.x, __expf(dot8(q0a, q0b, k2a, k2b)),
                            sB.x * __expf(dot8(q0a, q0b, k3a, k3b)));
                wv.y = fmaf(sA.y, __expf(dot8(q1a, q1b, k2a, k2b)),
                            sB.y * __expf(dot8(q1a, q1b, k3a, k3b)));
                *(float2*)(&s_w[n][mrow]) = wv;
            }
        }

        if (t + 1 < HT) {
#pragma unroll
            for (int k = 0; k < 4; k++) vr[k] = vg[(t0 + t + 1) * 1024 + tid + k * 256];
        }
        if (t + 2 < HT) {
            const int base = (t0 + t + 2) * 128;
            pr = (tid < 128) ? p2g[base + tid] : p3g[base + tid - 128];
        }
        __syncthreads();   // w(t), v(t) visible

#pragma unroll 8
        for (int nn = 0; nn < 32; nn++) {
            const int n = nlo + nn;
            const float4 w0 = *(const float4*)(&s_w[n][mg * 8]);
            const float4 w1 = *(const float4*)(&s_w[n][mg * 8 + 4]);
            const float4 vv = *(const float4*)(&s_v[n][cg * 4]);
            acc[0][0] = fmaf(w0.x, vv.x, acc[0][0]);
            acc[0][1] = fmaf(w0.x, vv.y, acc[0][1]);
            acc[0][2] = fmaf(w0.x, vv.z, acc[0][2]);
            acc[0][3] = fmaf(w0.x, vv.w, acc[0][3]);
            acc[1][0] = fmaf(w0.y, vv.x, acc[1][0]);
            acc[1][1] = fmaf(w0.y, vv.y, acc[1][1]);
            acc[1][2] = fmaf(w0.y, vv.z, acc[1][2]);
            acc[1][3] = fmaf(w0.y, vv.w, acc[1][3]);
            acc[2][0] = fmaf(w0.z, vv.x, acc[2][0]);
            acc[2][1] = fmaf(w0.z, vv.y, acc[2][1]);
            acc[2][2] = fmaf(w0.z, vv.z, acc[2][2]);
            acc[2][3] = fmaf(w0.z, vv.w, acc[2][3]);
            acc[3][0] = fmaf(w0.w, vv.x, acc[3][0]);
            acc[3][1] = fmaf(w0.w, vv.y, acc[3][1]);
            acc[3][2] = fmaf(w0.w, vv.z, acc[3][2]);
            acc[3][3] = fmaf(w0.w, vv.w, acc[3][3]);
            acc[4][0] = fmaf(w1.x, vv.x, acc[4][0]);
            acc[4][1] = fmaf(w1.x, vv.y, acc[4][1]);
            acc[4][2] = fmaf(w1.x, vv.z, acc[4][2]);
            acc[4][3] = fmaf(w1.x, vv.w, acc[4][3]);
            acc[5][0] = fmaf(w1.y, vv.x, acc[5][0]);
            acc[5][1] = fmaf(w1.y, vv.y, acc[5][1]);
            acc[5][2] = fmaf(w1.y, vv.z, acc[5][2]);
            acc[5][3] = fmaf(w1.y, vv.w, acc[5][3]);
            acc[6][0] = fmaf(w1.z, vv.x, acc[6][0]);
            acc[6][1] = fmaf(w1.z, vv.y, acc[6][1]);
            acc[6][2] = fmaf(w1.z, vv.z, acc[6][2]);
            acc[6][3] = fmaf(w1.z, vv.w, acc[6][3]);
            acc[7][0] = fmaf(w1.w, vv.x, acc[7][0]);
            acc[7][1] = fmaf(w1.w, vv.y, acc[7][1]);
            acc[7][2] = fmaf(w1.w, vv.z, acc[7][2]);
            acc[7][3] = fmaf(w1.w, vv.w, acc[7][3]);
        }
        __syncthreads();   // gemm done; buffers reusable
    }

    // ---------------- cross-half reduction + partial write ----------------
    float* s_red = &s_v[0][0];               // reuse as [64 m][65]
    __syncthreads();
    if (half == 1) {
#pragma unroll
        for (int r = 0; r < 8; r++)
#pragma unroll
            for (int j = 0; j < 4; j++)
                s_red[(mg * 8 + r) * 65 + cg * 4 + j] = acc[r][j];
    }
    __syncthreads();
    if (half == 0) {
        float* pb = g_part + ((size_t)h * NB + b) * NCH * NN;
#pragma unroll
        for (int j = 0; j < 4; j++) {
            const int c = cg * 4 + j;
#pragma unroll
            for (int rb = 0; rb < 2; rb++) {
                const int mm = m0 + mg * 8 + rb * 4;
                float4 o;
                o.x = acc[rb * 4 + 0][j] + s_red[(mg * 8 + rb * 4 + 0) * 65 + c];
                o.y = acc[rb * 4 + 1][j] + s_red[(mg * 8 + rb * 4 + 1) * 65 + c];
                o.z = acc[rb * 4 + 2][j] + s_red[(mg * 8 + rb * 4 + 2) * 65 + c];
                o.w = acc[rb * 4 + 3][j] + s_red[(mg * 8 + rb * 4 + 3) * 65 + c];
                *(float4*)(pb + (size_t)c * NN + mm) = o;
            }
        }
    }
}

// ---------------------------------------------------------------------------
// K4: out = part0 + part1 + residual x3. One float4 per thread.
// ---------------------------------------------------------------------------
__global__ __launch_bounds__(256) void combine_kernel(const float* __restrict__ x,
                                                      float* __restrict__ out)
{
    const int j4 = blockIdx.x * 256 + threadIdx.x;      // float4 index
    const int b  = j4 >> 16;                            // (j4*4) >> 18
    const float4 p0 = ((const float4*)g_part)[j4];
    const float4 p1 = ((const float4*)g_part)[NB * NCH * NN / 4 + j4];
    const float4 xv = ((const float4*)x)[j4 + (b << 16)];
    float4 o;
    o.x = p0.x + p1.x + xv.x;
    o.y = p0.y + p1.y + xv.y;
    o.z = p0.z + p1.z + xv.z;
    o.w = p0.w + p1.w + xv.w;
    ((float4*)out)[j4] = o;
}

extern "C" void kernel_launch(void* const* d_in, const int* in_sizes, int n_in,
                              void* d_out, int out_size)
{
    const float* x   = (const float*)d_in[0];
    const float* wq2 = (const float*)d_in[1];
    const float* bq2 = (const float*)d_in[2];
    const float* wq3 = (const float*)d_in[3];
    const float* bq3 = (const float*)d_in[4];
    const float* wv3 = (const float*)d_in[5];
    const float* bv3 = (const float*)d_in[6];
    const float* g2  = (const float*)d_in[7];
    const float* g3  = (const float*)d_in[8];
    float* out = (float*)d_out;

    proj_kernel<<<dim3(NN / 128, NB), 128>>>(x, wq2, bq2, wq3, bq3, wv3, bv3);
    sum_kernel<<<dim3(NN / MT, NB, NSPLIT), 256>>>();
    gemm_kernel<<<dim3(NN / MT, NB, NSPLIT), 256>>>(g2, g3);
    combine_kernel<<<dim3(NB * NCH * NN / 4 / 256), 256>>>(x, out);
}

// round 9
// speedup vs baseline: 1.6517x; 1.6517x over previous
#include <cuda_runtime.h>
#include <cstdint>

// Problem constants (fixed by setup_inputs): B=4, C=128, W=H=64
#define NB  4
#define NCH 64      // c_half = c_out
#define ND  8       // d_qk
#define NN  4096    // W*H tokens
#define MT  64      // query tile (rows per block)  -> grid 256
#define NT  64      // key tile
#define VPAD 72     // pad ≡ 8 (mod 32) -> conflict-free mma fragment loads
#define WPAD 72

// Scratch (no cudaMalloc allowed) — 16B aligned for vector access.
__device__ __align__(16) float g_p2t[NB * NN * ND];    // [b][n][8]
__device__ __align__(16) float g_p3t[NB * NN * ND];    // [b][n][8]
__device__ __align__(16) float g_v3t[NB * NN * NCH];   // [b][n][64] (tf32-rounded)

__device__ __forceinline__ float to_tf32(float x) {
    unsigned u;
    asm("cvt.rna.tf32.f32 %0, %1;" : "=r"(u) : "f"(x));
    return __uint_as_float(u);
}

// D(16x8) += A(16x8,row) * B(8x8,col)  — tf32 inputs, f32 accumulate
__device__ __forceinline__ void mma_tf32(float* c,
                                         unsigned a0, unsigned a1, unsigned a2, unsigned a3,
                                         unsigned b0, unsigned b1)
{
    asm volatile(
        "mma.sync.aligned.m16n8k8.row.col.f32.tf32.tf32.f32 "
        "{%0,%1,%2,%3}, {%4,%5,%6,%7}, {%8,%9}, {%0,%1,%2,%3};"
        : "+f"(c[0]), "+f"(c[1]), "+f"(c[2]), "+f"(c[3])
        : "r"(a0), "r"(a1), "r"(a2), "r"(a3), "r"(b0), "r"(b1));
}

// ---------------------------------------------------------------------------
// K1: 1x1-conv projections, written n-major. v stored tf32-rounded.
// ---------------------------------------------------------------------------
__global__ void proj_kernel(const float* __restrict__ x,
                            const float* __restrict__ wq2, const float* __restrict__ bq2,
                            const float* __restrict__ wq3, const float* __restrict__ bq3,
                            const float* __restrict__ wv3, const float* __restrict__ bv3)
{
    __shared__ float s_wq2[ND * NCH];
    __shared__ float s_wq3[ND * NCH];
    __shared__ float s_wv3[NCH * NCH];
    __shared__ float s_b[2 * ND + NCH];

    const int tid = threadIdx.x;
    for (int i = tid; i < ND * NCH; i += 128) { s_wq2[i] = wq2[i]; s_wq3[i] = wq3[i]; }
    for (int i = tid; i < NCH * NCH; i += 128) s_wv3[i] = wv3[i];
    if (tid < ND)                s_b[tid] = bq2[tid];
    else if (tid < 2 * ND)       s_b[tid] = bq3[tid - ND];
    else if (tid < 2 * ND + NCH) s_b[tid] = bv3[tid - 2 * ND];
    __syncthreads();

    const int b = blockIdx.y;
    const int n = blockIdx.x * 128 + tid;
    const float* xb = x + (size_t)b * (2 * NCH) * NN;

    float p2[ND], p3[ND], v[NCH];
#pragma unroll
    for (int d = 0; d < ND; d++) { p2[d] = s_b[d]; p3[d] = s_b[ND + d]; }
#pragma unroll
    for (int c = 0; c < NCH; c++) v[c] = s_b[2 * ND + c];

    for (int c = 0; c < NCH; c++) {
        const float x3v = xb[c * NN + n];
        const float x2v = xb[(NCH + c) * NN + n];
#pragma unroll
        for (int d = 0; d < ND; d++) {
            p2[d] = fmaf(s_wq2[d * NCH + c], x2v, p2[d]);
            p3[d] = fmaf(s_wq3[d * NCH + c], x3v, p3[d]);
        }
#pragma unroll
        for (int o = 0; o < NCH; o++)
            v[o] = fmaf(s_wv3[o * NCH + c], x3v, v[o]);
    }

    float* o2 = g_p2t + ((size_t)b * NN + n) * ND;
    float* o3 = g_p3t + ((size_t)b * NN + n) * ND;
    float* ov = g_v3t + ((size_t)b * NN + n) * NCH;
#pragma unroll
    for (int d = 0; d < ND; d++) { o2[d] = p2[d]; o3[d] = p3[d]; }
#pragma unroll
    for (int c = 0; c < NCH; c++) ov[c] = to_tf32(v[c]);
}

__device__ __forceinline__ float dot8(const float4 a, const float4 b,
                                      const float4 c, const float4 d)
{
    float s = a.x * c.x;
    s = fmaf(a.y, c.y, s);
    s = fmaf(a.z, c.z, s);
    s = fmaf(a.w, c.w, s);
    s = fmaf(b.x, d.x, s);
    s = fmaf(b.y, d.y, s);
    s = fmaf(b.z, d.z, s);
    s = fmaf(b.w, d.w, s);
    return s;
}

// ---------------------------------------------------------------------------
// K2: two-phase attention per (batch, 64-query tile). 256 threads.
//  Scores/weights: mq = tid&15 -> 4 query rows; np = tid>>4 -> keys n=i*16+np.
//  GEMM (tensor): warp w covers out[16m x 32c]: wm=(w&3)*16, wc=(w>>2)*32;
//  mma.m16n8k8.tf32: A = W^T slice (from s_w[n][m]), B = V (s_v[n][c]).
// ---------------------------------------------------------------------------
__global__ __launch_bounds__(256, 2) void att_kernel(const float* __restrict__ x,
                                                     const float* __restrict__ g2p,
                                                     const float* __restrict__ g3p,
                                                     float* __restrict__ out)
{
    __shared__ __align__(16) float s_p2[2][NT * ND];     // double-buffered [n][8]
    __shared__ __align__(16) float s_p3[2][NT * ND];
    __shared__ __align__(16) float s_v[NT][VPAD];        // [n][c]  (tf32 values)
    __shared__ __align__(16) float s_w[NT][WPAD];        // [n][m]  (tf32 values)
    __shared__ __align__(16) float s_q[MT * ND];         // stashed q rows
    __shared__ __align__(16) float s_sc32[MT];
    __shared__ __align__(16) float s_sc33[MT];

    const int tid = threadIdx.x;
    const int b   = blockIdx.y;
    const int m0  = blockIdx.x * MT;
    const int mq  = tid & 15;
    const int np  = tid >> 4;

    const float g2 = *g2p;
    const float g3 = *g3p;

    const float4* p2g = (const float4*)g_p2t + (size_t)b * NN * 2;
    const float4* p3g = (const float4*)g_p3t + (size_t)b * NN * 2;

    // 4 query rows (p3) in registers for phase 1
    float4 qa[4], qb[4];
#pragma unroll
    for (int k = 0; k < 4; k++) {
        qa[k] = p3g[(m0 + mq * 4 + k) * 2 + 0];
        qb[k] = p3g[(m0 + mq * 4 + k) * 2 + 1];
    }

    // ---------------- Phase 1: softmax denominators (max-free) ----------------
    float sum32[4] = {0.f, 0.f, 0.f, 0.f};
    float sum33[4] = {0.f, 0.f, 0.f, 0.f};
    float4 pr = (tid < 128) ? p2g[tid] : p3g[tid - 128];
    if (tid < 128) ((float4*)s_p2[0])[tid]       = pr;
    else           ((float4*)s_p3[0])[tid - 128] = pr;
    __syncthreads();
    for (int t = 0; t < NN / NT; t++) {
        const int cur = t & 1;
        if (t + 1 < NN / NT) {
            const int base = (t + 1) * NT * 2;
            pr = (tid < 128) ? p2g[base + tid] : p3g[base + tid - 128];
        }
#pragma unroll
        for (int i = 0; i < 4; i++) {
            const int n = i * 16 + np;
            const float4 k2a = ((const float4*)s_p2[cur])[n * 2];
            const float4 k2b = ((const float4*)s_p2[cur])[n * 2 + 1];
            const float4 k3a = ((const float4*)s_p3[cur])[n * 2];
            const float4 k3b = ((const float4*)s_p3[cur])[n * 2 + 1];
#pragma unroll
            for (int k = 0; k < 4; k++) {
                sum32[k] += __expf(dot8(qa[k], qb[k], k2a, k2b));
                sum33[k] += __expf(dot8(qa[k], qb[k], k3a, k3b));
            }
        }
        if (t + 1 < NN / NT) {
            if (tid < 128) ((float4*)s_p2[cur ^ 1])[tid]       = pr;
            else           ((float4*)s_p3[cur ^ 1])[tid - 128] = pr;
        }
        __syncthreads();
    }
#pragma unroll
    for (int k = 0; k < 4; k++) {
        sum32[k] += __shfl_xor_sync(0xffffffffu, sum32[k], 16);
        sum33[k] += __shfl_xor_sync(0xffffffffu, sum33[k], 16);
    }
    // cross-warp reduction through smem (stage in s_w)
    {
        float* s_red = &s_w[0][0];
        const int warp = tid >> 5, lane = tid & 31;
        if (lane < 16) {
#pragma unroll
            for (int k = 0; k < 4; k++) {
                s_red[(lane * 8 + warp) * 8 + k]     = sum32[k];
                s_red[(lane * 8 + warp) * 8 + 4 + k] = sum33[k];
            }
        }
        __syncthreads();
        if (tid < 128) {
            const int m = tid >> 1, type = tid & 1;
            const int mq_ = m >> 2, k_ = m & 3;
            float s = 0.f;
#pragma unroll
            for (int w = 0; w < 8; w++)
                s += s_red[(mq_ * 8 + w) * 8 + type * 4 + k_];
            if (type == 0) s_sc32[m] = g2 / s;
            else           s_sc33[m] = g3 / s;
        }
    }
    // stash q rows (frees registers for phase 2)
    if (np == 0) {
#pragma unroll
        for (int k = 0; k < 4; k++) {
            float4* d = (float4*)(s_q + (size_t)(mq * 4 + k) * ND);
            d[0] = qa[k];
            d[1] = qb[k];
        }
    }

    // ---------------- Phase 2: combined-weight tensor GEMM ----------------
    const float4* vg = (const float4*)g_v3t + (size_t)b * NN * (NCH / 4);
    const int warp = tid >> 5;
    const int lane = tid & 31;
    const int g8   = lane >> 2;              // fragment group 0..7
    const int l4   = lane & 3;               // thread-in-group
    const int wm   = (warp & 3) * 16;        // warp m-offset
    const int wc   = (warp >> 2) * 32;       // warp c-offset

    float acc[4][4];                         // 4 c-subtiles x 4 frag regs
#pragma unroll
    for (int ct = 0; ct < 4; ct++)
#pragma unroll
        for (int j = 0; j < 4; j++) acc[ct][j] = 0.f;

    // preamble: p-tile0 -> buf0, prefetch p-tile1 + v-tile0
    pr = (tid < 128) ? p2g[tid] : p3g[tid - 128];
    float4 vr[4];
#pragma unroll
    for (int k = 0; k < 4; k++) vr[k] = vg[tid + k * 256];
    if (tid < 128) ((float4*)s_p2[0])[tid]       = pr;
    else           ((float4*)s_p3[0])[tid - 128] = pr;
    pr = (tid < 128) ? p2g[NT * 2 + tid] : p3g[NT * 2 + tid - 128];
    __syncthreads();   // p buf0, s_sc, s_q ready; s_w staging free

    for (int t = 0; t < NN / NT; t++) {
        const int cur = t & 1;
        // fill v(t), stage p(t+1)
#pragma unroll
        for (int k = 0; k < 4; k++) {
            const int fi = tid + k * 256;
            *(float4*)(&s_v[fi >> 4][(fi & 15) * 4]) = vr[k];
        }
        if (t + 1 < NN / NT) {
            if (tid < 128) ((float4*)s_p2[cur ^ 1])[tid]       = pr;
            else           ((float4*)s_p3[cur ^ 1])[tid - 128] = pr;
        }

        // weight gen for tile t (two query rows at a time), tf32-rounded
#pragma unroll
        for (int kh = 0; kh < 2; kh++) {
            const int mrow = mq * 4 + kh * 2;
            const float4 q0a = ((const float4*)(s_q + (size_t)mrow * ND))[0];
            const float4 q0b = ((const float4*)(s_q + (size_t)mrow * ND))[1];
            const float4 q1a = ((const float4*)(s_q + (size_t)(mrow + 1) * ND))[0];
            const float4 q1b = ((const float4*)(s_q + (size_t)(mrow + 1) * ND))[1];
            const float2 sA = *(const float2*)&s_sc32[mrow];
            const float2 sB = *(const float2*)&s_sc33[mrow];
#pragma unroll
            for (int i = 0; i < 4; i++) {
                const int n = i * 16 + np;
                const float4 k2a = ((const float4*)s_p2[cur])[n * 2];
                const float4 k2b = ((const float4*)s_p2[cur])[n * 2 + 1];
                const float4 k3a = ((const float4*)s_p3[cur])[n * 2];
                const float4 k3b = ((const float4*)s_p3[cur])[n * 2 + 1];
                float2 wv;
                wv.x = to_tf32(fmaf(sA.x, __expf(dot8(q0a, q0b, k2a, k2b)),
                                    sB.x * __expf(dot8(q0a, q0b, k3a, k3b))));
                wv.y = to_tf32(fmaf(sA.y, __expf(dot8(q1a, q1b, k2a, k2b)),
                                    sB.y * __expf(dot8(q1a, q1b, k3a, k3b))));
                *(float2*)(&s_w[n][mrow]) = wv;
            }
        }

        // prefetch next tiles (lands during mma)
        if (t + 1 < NN / NT) {
#pragma unroll
            for (int k = 0; k < 4; k++) vr[k] = vg[(t + 1) * NT * 16 + tid + k * 256];
        }
        if (t + 2 < NN / NT) {
            const int base = (t + 2) * NT * 2;
            pr = (tid < 128) ? p2g[base + tid] : p3g[base + tid - 128];
        }
        __syncthreads();   // B: w(t), v(t) visible

        // tensor GEMM: out[16m x 32c] += W^T(16m x 64n) * V(64n x 32c)
#pragma unroll
        for (int kc = 0; kc < 8; kc++) {
            const int n0 = kc * 8;
            const unsigned a0 = __float_as_uint(s_w[n0 + l4][wm + g8]);
            const unsigned a1 = __float_as_uint(s_w[n0 + l4][wm + g8 + 8]);
            const unsigned a2 = __float_as_uint(s_w[n0 + l4 + 4][wm + g8]);
            const unsigned a3 = __float_as_uint(s_w[n0 + l4 + 4][wm + g8 + 8]);
#pragma unroll
            for (int ct = 0; ct < 4; ct++) {
                const int c = wc + ct * 8 + g8;
                const unsigned b0 = __float_as_uint(s_v[n0 + l4][c]);
                const unsigned b1 = __float_as_uint(s_v[n0 + l4 + 4][c]);
                mma_tf32(acc[ct], a0, a1, a2, a3, b0, b1);
            }
        }
        __syncthreads();   // A: mma reads done; buffers reusable
    }

    // ---------------- epilogue: stage frags -> coalesced write + residual ----
    float* s_red = &s_v[0][0];               // reuse as [64 m][72]
#pragma unroll
    for (int ct = 0; ct < 4; ct++) {
        const int c = wc + ct * 8 + 2 * l4;
        *(float2*)&s_red[(wm + g8) * 72 + c]     = make_float2(acc[ct][0], acc[ct][1]);
        *(float2*)&s_red[(wm + g8 + 8) * 72 + c] = make_float2(acc[ct][2], acc[ct][3]);
    }
    __syncthreads();
    {
        const float* xb = x + (size_t)b * (2 * NCH) * NN;   // x3 = channels 0..63
        float* ob = out + (size_t)b * NCH * NN;
#pragma unroll
        for (int j = 0; j < 4; j++) {
            const int idx = tid + j * 256;   // 0..1023 = 64c x 16 float4-of-m
            const int c   = idx >> 4;
            const int mf  = idx & 15;
            const float4 xv = *(const float4*)(xb + (size_t)c * NN + m0 + mf * 4);
            float4 o;
            o.x = s_red[(mf * 4 + 0) * 72 + c] + xv.x;
            o.y = s_red[(mf * 4 + 1) * 72 + c] + xv.y;
            o.z = s_red[(mf * 4 + 2) * 72 + c] + xv.z;
            o.w = s_red[(mf * 4 + 3) * 72 + c] + xv.w;
            *(float4*)(ob + (size_t)c * NN + m0 + mf * 4) = o;
        }
    }
}

extern "C" void kernel_launch(void* const* d_in, const int* in_sizes, int n_in,
                              void* d_out, int out_size)
{
    const float* x   = (const float*)d_in[0];
    const float* wq2 = (const float*)d_in[1];
    const float* bq2 = (const float*)d_in[2];
    const float* wq3 = (const float*)d_in[3];
    const float* bq3 = (const float*)d_in[4];
    const float* wv3 = (const float*)d_in[5];
    const float* bv3 = (const float*)d_in[6];
    const float* g2  = (const float*)d_in[7];
    const float* g3  = (const float*)d_in[8];
    float* out = (float*)d_out;

    proj_kernel<<<dim3(NN / 128, NB), 128>>>(x, wq2, bq2, wq3, bq3, wv3, bv3);
    att_kernel<<<dim3(NN / MT, NB), 256>>>(x, g2, g3, out);
}

// round 10
// speedup vs baseline: 4.6222x; 2.7984x over previous
#include <cuda_runtime.h>
#include <cuda_bf16.h>
#include <cstdint>

// Problem constants: B=4, C=128, W=H=64
#define NB  4
#define NCH 64
#define ND  8
#define NN  4096
#define MT  64      // query tile -> grid 256
#define NT  64      // key tile
#define EP  72      // e-tile pad (bf16 units): conflict-free A-frag loads
#define VP  72      // v-tile pad (bf16 units): conflict-free ldmatrix rows

// Scratch (no cudaMalloc allowed)
__device__ __align__(16) float         g_p2t[NB * NN * ND];   // tf32-rounded
__device__ __align__(16) float         g_p3t[NB * NN * ND];   // tf32-rounded
__device__ __align__(16) __nv_bfloat16 g_v3b[NB * NN * NCH];  // [b][n][c] bf16

__device__ __forceinline__ float to_tf32(float x) {
    unsigned u;
    asm("cvt.rna.tf32.f32 %0, %1;" : "=r"(u) : "f"(x));
    return __uint_as_float(u);
}
__device__ __forceinline__ unsigned pk_bf16x2(float lo, float hi) {
    unsigned r;
    asm("cvt.rn.bf16x2.f32 %0, %1, %2;" : "=r"(r) : "f"(hi), "f"(lo));
    return r;
}
// D += A(16x8 row, tf32) * B(8x8 col, tf32)
__device__ __forceinline__ void mma_tf32(float* c,
                                         unsigned a0, unsigned a1, unsigned a2, unsigned a3,
                                         unsigned b0, unsigned b1)
{
    asm volatile(
        "mma.sync.aligned.m16n8k8.row.col.f32.tf32.tf32.f32 "
        "{%0,%1,%2,%3}, {%4,%5,%6,%7}, {%8,%9}, {%0,%1,%2,%3};"
        : "+f"(c[0]), "+f"(c[1]), "+f"(c[2]), "+f"(c[3])
        : "r"(a0), "r"(a1), "r"(a2), "r"(a3), "r"(b0), "r"(b1));
}
// D += A(16x16 row, bf16) * B(16x8 col, bf16)
__device__ __forceinline__ void mma_bf16(float* c,
                                         unsigned a0, unsigned a1, unsigned a2, unsigned a3,
                                         unsigned b0, unsigned b1)
{
    asm volatile(
        "mma.sync.aligned.m16n8k16.row.col.f32.bf16.bf16.f32 "
        "{%0,%1,%2,%3}, {%4,%5,%6,%7}, {%8,%9}, {%0,%1,%2,%3};"
        : "+f"(c[0]), "+f"(c[1]), "+f"(c[2]), "+f"(c[3])
        : "r"(a0), "r"(a1), "r"(a2), "r"(a3), "r"(b0), "r"(b1));
}
__device__ __forceinline__ void ldsm_x2_trans(unsigned& r0, unsigned& r1, uint32_t addr)
{
    asm volatile("ldmatrix.sync.aligned.m8n8.x2.trans.shared.b16 {%0,%1}, [%2];"
                 : "=r"(r0), "=r"(r1) : "r"(addr));
}

// ---------------------------------------------------------------------------
// K1: projections. p2/p3 tf32-rounded n-major; v bf16 [b][n][c].
// ---------------------------------------------------------------------------
__global__ void proj_kernel(const float* __restrict__ x,
                            const float* __restrict__ wq2, const float* __restrict__ bq2,
                            const float* __restrict__ wq3, const float* __restrict__ bq3,
                            const float* __restrict__ wv3, const float* __restrict__ bv3)
{
    __shared__ float s_wq2[ND * NCH];
    __shared__ float s_wq3[ND * NCH];
    __shared__ float s_wv3[NCH * NCH];
    __shared__ float s_b[2 * ND + NCH];

    const int tid = threadIdx.x;
    for (int i = tid; i < ND * NCH; i += 128) { s_wq2[i] = wq2[i]; s_wq3[i] = wq3[i]; }
    for (int i = tid; i < NCH * NCH; i += 128) s_wv3[i] = wv3[i];
    if (tid < ND)                s_b[tid] = bq2[tid];
    else if (tid < 2 * ND)       s_b[tid] = bq3[tid - ND];
    else if (tid < 2 * ND + NCH) s_b[tid] = bv3[tid - 2 * ND];
    __syncthreads();

    const int b = blockIdx.y;
    const int n = blockIdx.x * 128 + tid;
    const float* xb = x + (size_t)b * (2 * NCH) * NN;

    float p2[ND], p3[ND], v[NCH];
#pragma unroll
    for (int d = 0; d < ND; d++) { p2[d] = s_b[d]; p3[d] = s_b[ND + d]; }
#pragma unroll
    for (int c = 0; c < NCH; c++) v[c] = s_b[2 * ND + c];

    for (int c = 0; c < NCH; c++) {
        const float x3v = xb[c * NN + n];
        const float x2v = xb[(NCH + c) * NN + n];
#pragma unroll
        for (int d = 0; d < ND; d++) {
            p2[d] = fmaf(s_wq2[d * NCH + c], x2v, p2[d]);
            p3[d] = fmaf(s_wq3[d * NCH + c], x3v, p3[d]);
        }
#pragma unroll
        for (int o = 0; o < NCH; o++)
            v[o] = fmaf(s_wv3[o * NCH + c], x3v, v[o]);
    }

    float* o2 = g_p2t + ((size_t)b * NN + n) * ND;
    float* o3 = g_p3t + ((size_t)b * NN + n) * ND;
    __nv_bfloat16* ov = g_v3b + ((size_t)b * NN + n) * NCH;
#pragma unroll
    for (int d = 0; d < ND; d++) { o2[d] = to_tf32(p2[d]); o3[d] = to_tf32(p3[d]); }
#pragma unroll
    for (int c = 0; c < NCH; c++) ov[c] = __float2bfloat16(v[c]);
}

// ---------------------------------------------------------------------------
// K2: single-pass dual attention per (batch, 64-query tile). 256 threads.
//  Warp w: wm=(w&3)*16 (m-block), wh=w>>2 (n-half for scores, c-half for out).
//  Per key tile: tf32 mma scores -> exp -> (Z sums in regs) + bf16 e-tiles
//  -> two bf16 mma GEMMs (unnormalized). Normalize once at the end.
// ---------------------------------------------------------------------------
__global__ __launch_bounds__(256, 2) void att_kernel(const float* __restrict__ x,
                                                     const float* __restrict__ g2p,
                                                     const float* __restrict__ g3p,
                                                     float* __restrict__ out)
{
    __shared__ __align__(16) float         s_p2[2][NT * ND];
    __shared__ __align__(16) float         s_p3[2][NT * ND];
    __shared__ __align__(16) __nv_bfloat16 s_v[NT * VP];      // [n][c]
    __shared__ __align__(16) __nv_bfloat16 s_e[2][MT * EP];   // e32,e33 [m][n]; aliased fp32 s_red
    __shared__ __align__(16) float s_z32[2][MT];
    __shared__ __align__(16) float s_z33[2][MT];
    __shared__ __align__(16) float s_f32[MT];
    __shared__ __align__(16) float s_f33[MT];

    const int tid  = threadIdx.x;
    const int b    = blockIdx.y;
    const int m0   = blockIdx.x * MT;
    const int warp = tid >> 5;
    const int lane = tid & 31;
    const int g8   = lane >> 2;
    const int l4   = lane & 3;
    const int wm   = (warp & 3) * 16;
    const int wh   = warp >> 2;
    const int wn   = wh * 32;           // score n-half
    const int wc   = wh * 32;           // out c-half

    const float g2 = *g2p;
    const float g3 = *g3p;

    const float4* p2g = (const float4*)g_p2t + (size_t)b * NN * 2;
    const float4* p3g = (const float4*)g_p3t + (size_t)b * NN * 2;
    const uint4*  vgb = (const uint4*)(g_v3b + (size_t)b * NN * NCH);

    // q A-fragment (fixed for whole kernel; values already tf32-rounded)
    const float* qb = g_p3t + ((size_t)b * NN + m0) * ND;
    const unsigned aq0 = __float_as_uint(qb[(wm + g8) * ND + l4]);
    const unsigned aq1 = __float_as_uint(qb[(wm + g8 + 8) * ND + l4]);
    const unsigned aq2 = __float_as_uint(qb[(wm + g8) * ND + l4 + 4]);
    const unsigned aq3 = __float_as_uint(qb[(wm + g8 + 8) * ND + l4 + 4]);

    float acc32[4][4], acc33[4][4];
#pragma unroll
    for (int ct = 0; ct < 4; ct++)
#pragma unroll
        for (int j = 0; j < 4; j++) { acc32[ct][j] = 0.f; acc33[ct][j] = 0.f; }
    float sum32a = 0.f, sum32b = 0.f, sum33a = 0.f, sum33b = 0.f;

    // preamble: stage p(0), prefetch p(1) + v(0)
    float4 pr = (tid < 128) ? p2g[tid] : p3g[tid - 128];
    if (tid < 128) ((float4*)s_p2[0])[tid]       = pr;
    else           ((float4*)s_p3[0])[tid - 128] = pr;
    pr = (tid < 128) ? p2g[128 + tid] : p3g[128 + tid - 128];
    uint4 vr0 = vgb[tid * 2];
    uint4 vr1 = vgb[tid * 2 + 1];
    __syncthreads();

    for (int t = 0; t < NN / NT; t++) {
        const int cur = t & 1;
        // stage v(t): [n][c] bf16, row stride VP
        {
            const int fi = tid * 2;
            *(uint4*)&s_v[(fi >> 3) * VP + (fi & 7) * 8]             = vr0;
            *(uint4*)&s_v[((fi + 1) >> 3) * VP + ((fi + 1) & 7) * 8] = vr1;
        }
        // stage p(t+1)
        if (t + 1 < NN / NT) {
            if (tid < 128) ((float4*)s_p2[cur ^ 1])[tid]       = pr;
            else           ((float4*)s_p3[cur ^ 1])[tid - 128] = pr;
        }

        // scores (tf32 mma) -> exp -> Z partials + bf16 e-tiles
        const float* P2 = s_p2[cur];
        const float* P3 = s_p3[cur];
#pragma unroll
        for (int i = 0; i < 4; i++) {
            const int n0 = wn + i * 8;
            float c2[4] = {0.f, 0.f, 0.f, 0.f};
            float c3[4] = {0.f, 0.f, 0.f, 0.f};
            const unsigned b20 = __float_as_uint(P2[(n0 + g8) * ND + l4]);
            const unsigned b21 = __float_as_uint(P2[(n0 + g8) * ND + l4 + 4]);
            const unsigned b30 = __float_as_uint(P3[(n0 + g8) * ND + l4]);
            const unsigned b31 = __float_as_uint(P3[(n0 + g8) * ND + l4 + 4]);
            mma_tf32(c2, aq0, aq1, aq2, aq3, b20, b21);
            mma_tf32(c3, aq0, aq1, aq2, aq3, b30, b31);
            const float e0 = __expf(c2[0]), e1 = __expf(c2[1]);
            const float e2 = __expf(c2[2]), e3 = __expf(c2[3]);
            sum32a += e0 + e1; sum32b += e2 + e3;
            *(unsigned*)&s_e[0][(wm + g8) * EP + n0 + 2 * l4]     = pk_bf16x2(e0, e1);
            *(unsigned*)&s_e[0][(wm + g8 + 8) * EP + n0 + 2 * l4] = pk_bf16x2(e2, e3);
            const float f0 = __expf(c3[0]), f1 = __expf(c3[1]);
            const float f2 = __expf(c3[2]), f3 = __expf(c3[3]);
            sum33a += f0 + f1; sum33b += f2 + f3;
            *(unsigned*)&s_e[1][(wm + g8) * EP + n0 + 2 * l4]     = pk_bf16x2(f0, f1);
            *(unsigned*)&s_e[1][(wm + g8 + 8) * EP + n0 + 2 * l4] = pk_bf16x2(f2, f3);
        }

        // prefetch next tiles
        if (t + 1 < NN / NT) {
            vr0 = vgb[(t + 1) * 512 + tid * 2];
            vr1 = vgb[(t + 1) * 512 + tid * 2 + 1];
        }
        if (t + 2 < NN / NT) {
            const int base = (t + 2) * 128;
            pr = (tid < 128) ? p2g[base + tid] : p3g[base + tid - 128];
        }
        __syncthreads();   // e(t), v(t) visible

        // out GEMMs (bf16): acc += E^T(16m x 64n) * V(64n x 32c), both atts
#pragma unroll
        for (int kc = 0; kc < 4; kc++) {
            const int kn = kc * 16;
            const unsigned a20 = *(const unsigned*)&s_e[0][(wm + g8) * EP + kn + 2 * l4];
            const unsigned a21 = *(const unsigned*)&s_e[0][(wm + g8 + 8) * EP + kn + 2 * l4];
            const unsigned a22 = *(const unsigned*)&s_e[0][(wm + g8) * EP + kn + 2 * l4 + 8];
            const unsigned a23 = *(const unsigned*)&s_e[0][(wm + g8 + 8) * EP + kn + 2 * l4 + 8];
            const unsigned a30 = *(const unsigned*)&s_e[1][(wm + g8) * EP + kn + 2 * l4];
            const unsigned a31 = *(const unsigned*)&s_e[1][(wm + g8 + 8) * EP + kn + 2 * l4];
            const unsigned a32 = *(const unsigned*)&s_e[1][(wm + g8) * EP + kn + 2 * l4 + 8];
            const unsigned a33 = *(const unsigned*)&s_e[1][(wm + g8 + 8) * EP + kn + 2 * l4 + 8];
#pragma unroll
            for (int ct = 0; ct < 4; ct++) {
                const int c0 = wc + ct * 8;
                unsigned b0, b1;
                const uint32_t addr = (uint32_t)__cvta_generic_to_shared(
                    &s_v[(kn + (lane & 15)) * VP + c0]);
                ldsm_x2_trans(b0, b1, addr);
                mma_bf16(acc32[ct], a20, a21, a22, a23, b0, b1);
                mma_bf16(acc33[ct], a30, a31, a32, a33, b0, b1);
            }
        }
        __syncthreads();   // e/v consumed
    }

    // ---------------- Z reduction + normalization factors ----------------
    sum32a += __shfl_xor_sync(0xffffffffu, sum32a, 1);
    sum32a += __shfl_xor_sync(0xffffffffu, sum32a, 2);
    sum32b += __shfl_xor_sync(0xffffffffu, sum32b, 1);
    sum32b += __shfl_xor_sync(0xffffffffu, sum32b, 2);
    sum33a += __shfl_xor_sync(0xffffffffu, sum33a, 1);
    sum33a += __shfl_xor_sync(0xffffffffu, sum33a, 2);
    sum33b += __shfl_xor_sync(0xffffffffu, sum33b, 1);
    sum33b += __shfl_xor_sync(0xffffffffu, sum33b, 2);
    if (l4 == 0) {
        s_z32[wh][wm + g8]     = sum32a;
        s_z32[wh][wm + g8 + 8] = sum32b;
        s_z33[wh][wm + g8]     = sum33a;
        s_z33[wh][wm + g8 + 8] = sum33b;
    }
    __syncthreads();
    if (tid < 64) {
        s_f32[tid] = g2 / (s_z32[0][tid] + s_z32[1][tid]);
        s_f33[tid] = g3 / (s_z33[0][tid] + s_z33[1][tid]);
    }
    __syncthreads();

    // ---------------- scale + stage + coalesced write ----------------
    float* s_red = (float*)s_e;              // [64][72] fp32 (exactly overlays s_e)
    const float f2a = s_f32[wm + g8],     f3a = s_f33[wm + g8];
    const float f2b = s_f32[wm + g8 + 8], f3b = s_f33[wm + g8 + 8];
#pragma unroll
    for (int ct = 0; ct < 4; ct++) {
        const int c = wc + ct * 8 + 2 * l4;
        float2 lo, hi;
        lo.x = f2a * acc32[ct][0] + f3a * acc33[ct][0];
        lo.y = f2a * acc32[ct][1] + f3a * acc33[ct][1];
        hi.x = f2b * acc32[ct][2] + f3b * acc33[ct][2];
        hi.y = f2b * acc32[ct][3] + f3b * acc33[ct][3];
        *(float2*)&s_red[(wm + g8) * 72 + c]     = lo;
        *(float2*)&s_red[(wm + g8 + 8) * 72 + c] = hi;
    }
    __syncthreads();
    {
        const float* xb = x + (size_t)b * (2 * NCH) * NN;   // x3 = channels 0..63
        float* ob = out + (size_t)b * NCH * NN;
#pragma unroll
        for (int j = 0; j < 4; j++) {
            const int idx = tid + j * 256;   // 64c x 16 float4-of-m
            const int c   = idx >> 4;
            const int mf  = idx & 15;
            const float4 xv = *(const float4*)(xb + (size_t)c * NN + m0 + mf * 4);
            float4 o;
            o.x = s_red[(mf * 4 + 0) * 72 + c] + xv.x;
            o.y = s_red[(mf * 4 + 1) * 72 + c] + xv.y;
            o.z = s_red[(mf * 4 + 2) * 72 + c] + xv.z;
            o.w = s_red[(mf * 4 + 3) * 72 + c] + xv.w;
            *(float4*)(ob + (size_t)c * NN + m0 + mf * 4) = o;
        }
    }
}

extern "C" void kernel_launch(void* const* d_in, const int* in_sizes, int n_in,
                              void* d_out, int out_size)
{
    const float* x   = (const float*)d_in[0];
    const float* wq2 = (const float*)d_in[1];
    const float* bq2 = (const float*)d_in[2];
    const float* wq3 = (const float*)d_in[3];
    const float* bq3 = (const float*)d_in[4];
    const float* wv3 = (const float*)d_in[5];
    const float* bv3 = (const float*)d_in[6];
    const float* g2  = (const float*)d_in[7];
    const float* g3  = (const float*)d_in[8];
    float* out = (float*)d_out;

    proj_kernel<<<dim3(NN / 128, NB), 128>>>(x, wq2, bq2, wq3, bq3, wv3, bv3);
    att_kernel<<<dim3(NN / MT, NB), 256>>>(x, g2, g3, out);
}